// round 1
// baseline (speedup 1.0000x reference)
#include <cuda_runtime.h>
#include <cstdint>

// Scratch for segment start offsets (exclusive prefix sum of obj_size).
// Static __device__ array: allowed (no dynamic allocation).
#define MAX_SEGS 65536
__device__ int g_starts[MAX_SEGS];

// ---------------------------------------------------------------------------
// Kernel 1: single-block exclusive scan of obj_size -> g_starts.
// n <= MAX_SEGS. blockDim = 1024.
// ---------------------------------------------------------------------------
__global__ void scan_sizes_kernel(const int* __restrict__ sz, int n) {
    __shared__ int s_sums[1024];
    const int t = threadIdx.x;
    const int ipt = (n + 1023) / 1024;           // items per thread
    const int beg = t * ipt;
    const int end = min(n, beg + ipt);

    // local sum of this thread's chunk
    int local = 0;
    for (int i = beg; i < end; ++i) local += sz[i];
    s_sums[t] = local;
    __syncthreads();

    // serial exclusive scan of 1024 thread sums by thread 0 (fast enough)
    if (t == 0) {
        int run = 0;
        #pragma unroll 8
        for (int i = 0; i < 1024; ++i) {
            int v = s_sums[i];
            s_sums[i] = run;
            run += v;
        }
    }
    __syncthreads();

    // write exclusive starts for this chunk
    int run = s_sums[t];
    for (int i = beg; i < end; ++i) {
        g_starts[i] = run;
        run += sz[i];
    }
}

// ---------------------------------------------------------------------------
// Kernel 2: one CTA per segment. 128 threads = 4 warps.
// Lane l owns float4-column l (16 bytes); a warp covers a full 512B row.
// Warps stride rows by 4. Cross-warp reduce in smem, warp 0 writes mean.
// ---------------------------------------------------------------------------
__global__ __launch_bounds__(128, 16)
void seg_mean_kernel(const float* __restrict__ data,
                     const int* __restrict__ sz,
                     float* __restrict__ out) {
    const int seg = blockIdx.x;
    const int t = threadIdx.x;
    const int w = t >> 5;          // warp 0..3
    const int l = t & 31;          // lane 0..31

    const int start = g_starts[seg];
    const int len   = sz[seg];

    // float4 view: each row is 32 float4s
    const float4* __restrict__ base =
        reinterpret_cast<const float4*>(data) + (size_t)start * 32 + l;

    float4 acc = make_float4(0.f, 0.f, 0.f, 0.f);

    int r = w;
    // main unrolled loop: 4 independent loads in flight per thread
    #pragma unroll 1
    for (; r + 12 < len; r += 16) {
        float4 v0 = base[(size_t)(r     ) * 32];
        float4 v1 = base[(size_t)(r +  4) * 32];
        float4 v2 = base[(size_t)(r +  8) * 32];
        float4 v3 = base[(size_t)(r + 12) * 32];
        acc.x += v0.x; acc.y += v0.y; acc.z += v0.z; acc.w += v0.w;
        acc.x += v1.x; acc.y += v1.y; acc.z += v1.z; acc.w += v1.w;
        acc.x += v2.x; acc.y += v2.y; acc.z += v2.z; acc.w += v2.w;
        acc.x += v3.x; acc.y += v3.y; acc.z += v3.z; acc.w += v3.w;
    }
    for (; r < len; r += 4) {
        float4 v = base[(size_t)r * 32];
        acc.x += v.x; acc.y += v.y; acc.z += v.z; acc.w += v.w;
    }

    __shared__ float4 sm[4][32];
    sm[w][l] = acc;
    __syncthreads();

    if (w == 0) {
        float4 a = sm[0][l];
        float4 b = sm[1][l];
        float4 c = sm[2][l];
        float4 d = sm[3][l];
        const float inv = (len > 0) ? (1.0f / (float)len) : 0.0f;
        float4 o;
        o.x = (a.x + b.x + c.x + d.x) * inv;
        o.y = (a.y + b.y + c.y + d.y) * inv;
        o.z = (a.z + b.z + c.z + d.z) * inv;
        o.w = (a.w + b.w + c.w + d.w) * inv;
        reinterpret_cast<float4*>(out)[(size_t)seg * 32 + l] = o;
    }
}

// ---------------------------------------------------------------------------
// kernel_launch
// Inputs (metadata order): d_in[0] = data (float32, TOTAL_POINTS*128),
//                          d_in[1] = obj_size (int32, N_SEGMENTS)
// Output: float32 [N_SEGMENTS, 128]
// ---------------------------------------------------------------------------
extern "C" void kernel_launch(void* const* d_in, const int* in_sizes, int n_in,
                              void* d_out, int out_size) {
    const float* data = (const float*)d_in[0];
    const int*   sz   = (const int*)d_in[1];
    float*       out  = (float*)d_out;
    const int n_seg = in_sizes[1];

    scan_sizes_kernel<<<1, 1024>>>(sz, n_seg);
    seg_mean_kernel<<<n_seg, 128>>>(data, sz, out);
}

// round 2
// speedup vs baseline: 1.1078x; 1.1078x over previous
#include <cuda_runtime.h>
#include <cstdint>

// Scratch for segment start offsets (exclusive prefix sum of obj_size).
#define MAX_SEGS 65536
__device__ int g_starts[MAX_SEGS];

// ---------------------------------------------------------------------------
// Kernel 1: single-block hierarchical exclusive scan of obj_size -> g_starts.
// 1024 threads, each owns a contiguous chunk of ceil(n/1024) elements.
// local-sum -> warp shfl scan -> warp-total scan by warp 0 -> apply.
// ---------------------------------------------------------------------------
__global__ void scan_sizes_kernel(const int* __restrict__ sz, int n) {
    __shared__ int s_warp_tot[32];
    __shared__ int s_warp_off[32];

    const int t    = threadIdx.x;
    const int lane = t & 31;
    const int wid  = t >> 5;
    const int ipt  = (n + 1023) / 1024;
    const int beg  = t * ipt;
    const int end  = min(n, beg + ipt);

    // local chunk values + sum (keep in registers; ipt is small, <=64)
    int vals[64];
    int local = 0;
    #pragma unroll 4
    for (int i = beg; i < end; ++i) {
        int v = sz[i];
        vals[i - beg] = v;
        local += v;
    }

    // inclusive warp scan of local sums
    int inc = local;
    #pragma unroll
    for (int d = 1; d < 32; d <<= 1) {
        int u = __shfl_up_sync(0xFFFFFFFFu, inc, d);
        if (lane >= d) inc += u;
    }
    if (lane == 31) s_warp_tot[wid] = inc;
    __syncthreads();

    // warp 0 scans the 32 warp totals (exclusive)
    if (wid == 0) {
        int wv = s_warp_tot[lane];
        int winc = wv;
        #pragma unroll
        for (int d = 1; d < 32; d <<= 1) {
            int u = __shfl_up_sync(0xFFFFFFFFu, winc, d);
            if (lane >= d) winc += u;
        }
        s_warp_off[lane] = winc - wv;   // exclusive
    }
    __syncthreads();

    // exclusive prefix for this thread's chunk
    int run = s_warp_off[wid] + (inc - local);
    for (int i = beg; i < end; ++i) {
        g_starts[i] = run;
        run += vals[i - beg];
    }
}

// ---------------------------------------------------------------------------
// Kernel 2: one CTA per segment. 128 threads = 4 warps.
// Lane l owns float4-column l; a warp covers a full 512B row.
// Warps stride rows by 4. Fast path for len==64 with MLP=8 streaming loads.
// ---------------------------------------------------------------------------
__global__ __launch_bounds__(128)
void seg_mean_kernel(const float* __restrict__ data,
                     const int* __restrict__ sz,
                     float* __restrict__ out) {
    const int seg = blockIdx.x;
    const int t = threadIdx.x;
    const int w = t >> 5;          // warp 0..3
    const int l = t & 31;          // lane 0..31

    const int start = g_starts[seg];
    const int len   = sz[seg];

    const float4* __restrict__ base =
        reinterpret_cast<const float4*>(data) + (size_t)start * 32 + l;

    float4 acc = make_float4(0.f, 0.f, 0.f, 0.f);

    if (len == 64) {
        // thread handles rows w, w+4, ..., w+60 : 16 rows in 2 batches of 8
        #pragma unroll
        for (int b = 0; b < 2; ++b) {
            float4 v[8];
            #pragma unroll
            for (int i = 0; i < 8; ++i)
                v[i] = __ldcs(&base[(size_t)(w + (b * 8 + i) * 4) * 32]);
            #pragma unroll
            for (int i = 0; i < 8; ++i) {
                acc.x += v[i].x; acc.y += v[i].y;
                acc.z += v[i].z; acc.w += v[i].w;
            }
        }
    } else {
        int r = w;
        for (; r + 12 < len; r += 16) {
            float4 v0 = __ldcs(&base[(size_t)(r     ) * 32]);
            float4 v1 = __ldcs(&base[(size_t)(r +  4) * 32]);
            float4 v2 = __ldcs(&base[(size_t)(r +  8) * 32]);
            float4 v3 = __ldcs(&base[(size_t)(r + 12) * 32]);
            acc.x += v0.x + v1.x + v2.x + v3.x;
            acc.y += v0.y + v1.y + v2.y + v3.y;
            acc.z += v0.z + v1.z + v2.z + v3.z;
            acc.w += v0.w + v1.w + v2.w + v3.w;
        }
        for (; r < len; r += 4) {
            float4 v = __ldcs(&base[(size_t)r * 32]);
            acc.x += v.x; acc.y += v.y; acc.z += v.z; acc.w += v.w;
        }
    }

    __shared__ float4 sm[4][32];
    sm[w][l] = acc;
    __syncthreads();

    if (w == 0) {
        float4 a = sm[0][l];
        float4 b = sm[1][l];
        float4 c = sm[2][l];
        float4 d = sm[3][l];
        const float inv = (len > 0) ? (1.0f / (float)len) : 0.0f;
        float4 o;
        o.x = (a.x + b.x + c.x + d.x) * inv;
        o.y = (a.y + b.y + c.y + d.y) * inv;
        o.z = (a.z + b.z + c.z + d.z) * inv;
        o.w = (a.w + b.w + c.w + d.w) * inv;
        __stcs(&reinterpret_cast<float4*>(out)[(size_t)seg * 32 + l], o);
    }
}

// ---------------------------------------------------------------------------
// kernel_launch
// Inputs: d_in[0] = data (float32, TOTAL_POINTS*128),
//         d_in[1] = obj_size (int32, N_SEGMENTS)
// Output: float32 [N_SEGMENTS, 128]
// ---------------------------------------------------------------------------
extern "C" void kernel_launch(void* const* d_in, const int* in_sizes, int n_in,
                              void* d_out, int out_size) {
    const float* data = (const float*)d_in[0];
    const int*   sz   = (const int*)d_in[1];
    float*       out  = (float*)d_out;
    const int n_seg = in_sizes[1];

    scan_sizes_kernel<<<1, 1024>>>(sz, n_seg);
    seg_mean_kernel<<<n_seg, 128>>>(data, sz, out);
}

// round 3
// speedup vs baseline: 1.2418x; 1.1209x over previous
#include <cuda_runtime.h>
#include <cstdint>

#define MAX_SEGS    65536
#define SCAN_BLK    1024
#define MAX_BLOCKS  64          // supports n_seg <= 65536

__device__ int g_starts[MAX_SEGS];     // block-local exclusive prefix
__device__ int g_blocktot[MAX_BLOCKS]; // per-block totals
__device__ int g_blockoff[MAX_BLOCKS]; // exclusive prefix of block totals

// ---------------------------------------------------------------------------
// K1: per-block exclusive scan. grid = ceil(n/1024), block = 1024.
// Coalesced: 1 int load + 1 int store per thread.
// ---------------------------------------------------------------------------
__global__ void scan_local_kernel(const int* __restrict__ sz, int n) {
    __shared__ int s_tot[32];
    __shared__ int s_off[32];

    const int t    = threadIdx.x;
    const int lane = t & 31;
    const int wid  = t >> 5;
    const int gidx = blockIdx.x * SCAN_BLK + t;

    int v = (gidx < n) ? sz[gidx] : 0;

    // warp inclusive scan
    int inc = v;
    #pragma unroll
    for (int d = 1; d < 32; d <<= 1) {
        int u = __shfl_up_sync(0xFFFFFFFFu, inc, d);
        if (lane >= d) inc += u;
    }
    if (lane == 31) s_tot[wid] = inc;
    __syncthreads();

    // warp 0 scans the 32 warp totals
    if (wid == 0) {
        int wv = s_tot[lane];
        int winc = wv;
        #pragma unroll
        for (int d = 1; d < 32; d <<= 1) {
            int u = __shfl_up_sync(0xFFFFFFFFu, winc, d);
            if (lane >= d) winc += u;
        }
        s_off[lane] = winc - wv;            // exclusive warp offset
        if (lane == 31) g_blocktot[blockIdx.x] = winc;  // block total
    }
    __syncthreads();

    if (gidx < n) g_starts[gidx] = s_off[wid] + (inc - v);
}

// ---------------------------------------------------------------------------
// K2: single warp scans <=64 block totals -> exclusive g_blockoff.
// ---------------------------------------------------------------------------
__global__ void scan_blocks_kernel(int nb) {
    const int lane = threadIdx.x;   // 32 threads

    int v0 = (lane      < nb) ? g_blocktot[lane]      : 0;
    int v1 = (lane + 32 < nb) ? g_blocktot[lane + 32] : 0;

    int inc0 = v0;
    #pragma unroll
    for (int d = 1; d < 32; d <<= 1) {
        int u = __shfl_up_sync(0xFFFFFFFFu, inc0, d);
        if (lane >= d) inc0 += u;
    }
    int tot0 = __shfl_sync(0xFFFFFFFFu, inc0, 31);

    int inc1 = v1;
    #pragma unroll
    for (int d = 1; d < 32; d <<= 1) {
        int u = __shfl_up_sync(0xFFFFFFFFu, inc1, d);
        if (lane >= d) inc1 += u;
    }

    if (lane      < nb) g_blockoff[lane]      = inc0 - v0;
    if (lane + 32 < nb) g_blockoff[lane + 32] = inc1 - v1 + tot0;
}

// ---------------------------------------------------------------------------
// K3: one CTA per segment. 128 threads = 4 warps.
// Lane l owns float4-column l; warps stride rows by 4.
// Fast path for len==64 with MLP=8 streaming loads.
// ---------------------------------------------------------------------------
__global__ __launch_bounds__(128)
void seg_mean_kernel(const float* __restrict__ data,
                     const int* __restrict__ sz,
                     float* __restrict__ out) {
    const int seg = blockIdx.x;
    const int t = threadIdx.x;
    const int w = t >> 5;
    const int l = t & 31;

    const int start = g_blockoff[seg >> 10] + g_starts[seg];
    const int len   = sz[seg];

    const float4* __restrict__ base =
        reinterpret_cast<const float4*>(data) + (size_t)start * 32 + l;

    float4 acc = make_float4(0.f, 0.f, 0.f, 0.f);

    if (len == 64) {
        #pragma unroll
        for (int b = 0; b < 2; ++b) {
            float4 v[8];
            #pragma unroll
            for (int i = 0; i < 8; ++i)
                v[i] = __ldcs(&base[(size_t)(w + (b * 8 + i) * 4) * 32]);
            #pragma unroll
            for (int i = 0; i < 8; ++i) {
                acc.x += v[i].x; acc.y += v[i].y;
                acc.z += v[i].z; acc.w += v[i].w;
            }
        }
    } else {
        int r = w;
        for (; r + 12 < len; r += 16) {
            float4 v0 = __ldcs(&base[(size_t)(r     ) * 32]);
            float4 v1 = __ldcs(&base[(size_t)(r +  4) * 32]);
            float4 v2 = __ldcs(&base[(size_t)(r +  8) * 32]);
            float4 v3 = __ldcs(&base[(size_t)(r + 12) * 32]);
            acc.x += v0.x + v1.x + v2.x + v3.x;
            acc.y += v0.y + v1.y + v2.y + v3.y;
            acc.z += v0.z + v1.z + v2.z + v3.z;
            acc.w += v0.w + v1.w + v2.w + v3.w;
        }
        for (; r < len; r += 4) {
            float4 v = __ldcs(&base[(size_t)r * 32]);
            acc.x += v.x; acc.y += v.y; acc.z += v.z; acc.w += v.w;
        }
    }

    __shared__ float4 sm[4][32];
    sm[w][l] = acc;
    __syncthreads();

    if (w == 0) {
        float4 a = sm[0][l];
        float4 b = sm[1][l];
        float4 c = sm[2][l];
        float4 d = sm[3][l];
        const float inv = (len > 0) ? (1.0f / (float)len) : 0.0f;
        float4 o;
        o.x = (a.x + b.x + c.x + d.x) * inv;
        o.y = (a.y + b.y + c.y + d.y) * inv;
        o.z = (a.z + b.z + c.z + d.z) * inv;
        o.w = (a.w + b.w + c.w + d.w) * inv;
        __stcs(&reinterpret_cast<float4*>(out)[(size_t)seg * 32 + l], o);
    }
}

// ---------------------------------------------------------------------------
// kernel_launch
// ---------------------------------------------------------------------------
extern "C" void kernel_launch(void* const* d_in, const int* in_sizes, int n_in,
                              void* d_out, int out_size) {
    const float* data = (const float*)d_in[0];
    const int*   sz   = (const int*)d_in[1];
    float*       out  = (float*)d_out;
    const int n_seg = in_sizes[1];
    const int nb    = (n_seg + SCAN_BLK - 1) / SCAN_BLK;

    scan_local_kernel<<<nb, SCAN_BLK>>>(sz, n_seg);
    scan_blocks_kernel<<<1, 32>>>(nb);
    seg_mean_kernel<<<n_seg, 128>>>(data, sz, out);
}